// round 5
// baseline (speedup 1.0000x reference)
#include <cuda_runtime.h>
#include <math_constants.h>

// Problem shape (fixed by setup_inputs)
#define BB 2
#define NN 8192
#define MM 8192
#define FF 128
#define KEEP 4               // survivors kept per split (safety margin for approx ranking)
#define SPLITS 4
#define TILE (NN / SPLITS)   // 2048 candidates per split
#define BLK1 64              // targets per block in scan kernel

// Scratch (no cudaMalloc allowed): survivor indices only
__device__ int4 g_cand[BB * MM * SPLITS];

// Reference-matching sum of squares: ((x*x + y*y) + z*z), all ops rn, no fma
__device__ __forceinline__ float sumsq_ref(float x, float y, float z) {
    return __fadd_rn(__fadd_rn(__fmul_rn(x, x), __fmul_rn(y, y)), __fmul_rn(z, z));
}

// Branchless sorted insert (descending scores b0>=b1>=b2>=b3), guarded by s>b3.
#define INS(s, idx) do {                                                   \
    if ((s) > b3) {                                                        \
        bool g0 = (s) > b0, g1 = (s) > b1, g2 = (s) > b2;                  \
        float nv2 = g1 ? b1 : (s); int ni2 = g1 ? i1 : (idx);              \
        float nv1 = g0 ? b0 : (s); int ni1 = g0 ? i0 : (idx);              \
        b3 = g2 ? b2  : (s);  i3 = g2 ? i2  : (idx);                       \
        b2 = g2 ? nv2 : b2;   i2 = g2 ? ni2 : i2;                          \
        b1 = g1 ? nv1 : b1;   i1 = g1 ? ni1 : i1;                          \
        b0 = g0 ? (s) : b0;   i0 = g0 ? (idx) : i0;                        \
    }                                                                      \
} while (0)

// ---------------------------------------------------------------------------
// Kernel 1: brute-force scan. Approximate ranking by FMA score
//   s = x*tx + y*ty + z*tz - 0.5*|p|^2   (max s ~ min d2, within ~2e-7)
// Keeps top-4 indices per split; exact reference selection happens in merge.
// ---------------------------------------------------------------------------
__global__ void __launch_bounds__(BLK1) knn_scan(const float* __restrict__ spc,
                                                 const float* __restrict__ tpc) {
    __shared__ float4 tile[TILE];

    const int b     = blockIdx.z;
    const int split = blockIdx.y;
    const int m     = blockIdx.x * BLK1 + threadIdx.x;
    const int nbase = split * TILE;

    // Stage candidates, folding -0.5*|p|^2 (prep fused here)
    const float* __restrict__ sp = spc + (size_t)(b * NN + nbase) * 3;
    for (int i = threadIdx.x; i < TILE; i += BLK1) {
        float x = sp[3 * i + 0], y = sp[3 * i + 1], z = sp[3 * i + 2];
        tile[i] = make_float4(x, y, z, -0.5f * sumsq_ref(x, y, z));
    }

    const float* tp = tpc + (size_t)(b * MM + m) * 3;
    const float tx = tp[0], ty = tp[1], tz = tp[2];

    __syncthreads();

    float b0 = -CUDART_INF_F, b1 = -CUDART_INF_F, b2 = -CUDART_INF_F, b3 = -CUDART_INF_F;
    int   i0 = 0, i1 = 0, i2 = 0, i3 = 0;

#pragma unroll 4
    for (int i = 0; i < TILE; i += 4) {
        float4 p0 = tile[i + 0];
        float4 p1 = tile[i + 1];
        float4 p2 = tile[i + 2];
        float4 p3 = tile[i + 3];
        float s0 = __fmaf_rn(p0.x, tx, __fmaf_rn(p0.y, ty, __fmaf_rn(p0.z, tz, p0.w)));
        float s1 = __fmaf_rn(p1.x, tx, __fmaf_rn(p1.y, ty, __fmaf_rn(p1.z, tz, p1.w)));
        float s2 = __fmaf_rn(p2.x, tx, __fmaf_rn(p2.y, ty, __fmaf_rn(p2.z, tz, p2.w)));
        float s3 = __fmaf_rn(p3.x, tx, __fmaf_rn(p3.y, ty, __fmaf_rn(p3.z, tz, p3.w)));
        float mx = fmaxf(fmaxf(s0, s1), fmaxf(s2, s3));
        if (mx > b3) {
            INS(s0, i + 0);
            INS(s1, i + 1);
            INS(s2, i + 2);
            INS(s3, i + 3);
        }
    }

    g_cand[((size_t)(b * MM + m)) * SPLITS + split] =
        make_int4(nbase + i0, nbase + i1, nbase + i2, nbase + i3);
}

// ---------------------------------------------------------------------------
// Kernel 2: merge 4x4 survivors with the EXACT reference key
//   cross = ((x*tx + y*ty) + z*tz) all rn no-fma; d2 = (t2+s2)-(c+c);
//   d = sqrt(max(d2,0)); tie -> lower index (stable top_k).
// Then ref-rounded weights + warp-wide float4 feature blend.
// ---------------------------------------------------------------------------
__device__ __forceinline__ bool key_lt(float dA, int iA, float dB, int iB) {
    return (dA < dB) || (dA == dB && iA < iB);
}

__global__ void __launch_bounds__(256) merge_gather(const float* __restrict__ spc,
                                                    const float* __restrict__ tpc,
                                                    const float* __restrict__ sfeat,
                                                    float* __restrict__ out) {
    const int gwarp = (blockIdx.x * blockDim.x + threadIdx.x) >> 5;
    const int lane  = threadIdx.x & 31;
    const int b     = gwarp / MM;
    const int m     = gwarp % MM;

    const float* tp = tpc + (size_t)(b * MM + m) * 3;
    const float tx = tp[0], ty = tp[1], tz = tp[2];
    const float t2 = sumsq_ref(tx, ty, tz);
    const float* __restrict__ sp = spc + (size_t)b * NN * 3;

    float d0 = CUDART_INF_F, d1 = CUDART_INF_F, d2 = CUDART_INF_F;
    int   i0 = 0x7FFFFFFF,  i1 = 0x7FFFFFFF,  i2 = 0x7FFFFFFF;

#pragma unroll
    for (int sx = 0; sx < SPLITS; ++sx) {
        int4 c4 = g_cand[((size_t)(b * MM + m)) * SPLITS + sx];
        int idxs[KEEP] = {c4.x, c4.y, c4.z, c4.w};
#pragma unroll
        for (int j = 0; j < KEEP; ++j) {
            int   ix = idxs[j];
            float x = sp[3 * ix + 0], y = sp[3 * ix + 1], z = sp[3 * ix + 2];
            // exact reference arithmetic: mul+add cross, rn everywhere
            float c  = __fadd_rn(__fadd_rn(__fmul_rn(x, tx), __fmul_rn(y, ty)),
                                 __fmul_rn(z, tz));
            float dq = __fsub_rn(__fadd_rn(t2, sumsq_ref(x, y, z)), __fadd_rn(c, c));
            float dd = __fsqrt_rn(fmaxf(dq, 0.0f));
            if (key_lt(dd, ix, d2, i2)) {
                if (key_lt(dd, ix, d0, i0))      { d2=d1; i2=i1; d1=d0; i1=i0; d0=dd; i0=ix; }
                else if (key_lt(dd, ix, d1, i1)) { d2=d1; i2=i1; d1=dd; i1=ix; }
                else                             { d2=dd; i2=ix; }
            }
        }
    }

    // w = 1/(d + 1e-6); weight = w / sum(w), ascending-k order, all rn
    float w0 = __fdiv_rn(1.0f, __fadd_rn(d0, 1e-6f));
    float w1 = __fdiv_rn(1.0f, __fadd_rn(d1, 1e-6f));
    float w2 = __fdiv_rn(1.0f, __fadd_rn(d2, 1e-6f));
    float s  = __fadd_rn(__fadd_rn(w0, w1), w2);
    w0 = __fdiv_rn(w0, s);
    w1 = __fdiv_rn(w1, s);
    w2 = __fdiv_rn(w2, s);

    const float4* __restrict__ r0 = (const float4*)(sfeat + (size_t)(b * NN + i0) * FF);
    const float4* __restrict__ r1 = (const float4*)(sfeat + (size_t)(b * NN + i1) * FF);
    const float4* __restrict__ r2 = (const float4*)(sfeat + (size_t)(b * NN + i2) * FF);

    float4 v0 = r0[lane];
    float4 v1 = r1[lane];
    float4 v2 = r2[lane];

    // sum over K ascending, mul then add, all rn (matches jnp.sum)
    float4 o;
    o.x = __fadd_rn(__fadd_rn(__fmul_rn(v0.x, w0), __fmul_rn(v1.x, w1)), __fmul_rn(v2.x, w2));
    o.y = __fadd_rn(__fadd_rn(__fmul_rn(v0.y, w0), __fmul_rn(v1.y, w1)), __fmul_rn(v2.y, w2));
    o.z = __fadd_rn(__fadd_rn(__fmul_rn(v0.z, w0), __fmul_rn(v1.z, w1)), __fmul_rn(v2.z, w2));
    o.w = __fadd_rn(__fadd_rn(__fmul_rn(v0.w, w0), __fmul_rn(v1.w, w1)), __fmul_rn(v2.w, w2));

    float4* op = (float4*)(out + (size_t)(b * MM + m) * FF);
    op[lane] = o;
}

// ---------------------------------------------------------------------------
extern "C" void kernel_launch(void* const* d_in, const int* in_sizes, int n_in,
                              void* d_out, int out_size) {
    const float* source_pc   = (const float*)d_in[0];
    const float* target_pc   = (const float*)d_in[1];
    const float* source_feat = (const float*)d_in[2];
    float*       out         = (float*)d_out;

    dim3 g1(MM / BLK1, SPLITS, BB);   // 128 x 4 x 2 = 1024 blocks
    knn_scan<<<g1, BLK1>>>(source_pc, target_pc);

    const int warps = BB * MM;        // 16384
    merge_gather<<<warps / 8, 256>>>(source_pc, target_pc, source_feat, out);
}

// round 9
// speedup vs baseline: 1.0019x; 1.0019x over previous
#include <cuda_runtime.h>
#include <math_constants.h>

// Problem shape (fixed by setup_inputs)
#define BB 2
#define NN 8192
#define MM 8192
#define FF 128
#define KEEP 4                 // survivors per split (approx-ranking safety)
#define SPLITS 2
#define LSPLIT (NN / SPLITS)   // 4096 candidates per split
#define CHUNK 2048             // smem chunk (32 KB of float4)
#define NPH (LSPLIT / CHUNK)   // 2 phases
#define BLK1 64                // targets per block in scan kernel

// Scratch (no cudaMalloc allowed): survivor indices only
__device__ int4 g_cand[BB * MM * SPLITS];

// Reference-matching sum of squares: ((x*x + y*y) + z*z), all rn, no fma
__device__ __forceinline__ float sumsq_ref(float x, float y, float z) {
    return __fadd_rn(__fadd_rn(__fmul_rn(x, x), __fmul_rn(y, y)), __fmul_rn(z, z));
}

// Guarded branchless sorted insert (descending scores b0>=b1>=b2>=b3).
// Proven-clean construct (R5). Single guard, FSETP+SEL body, no nested branches.
#define INS(s, idx) do {                                                   \
    if ((s) > b3) {                                                        \
        bool g0 = (s) > b0, g1 = (s) > b1, g2 = (s) > b2;                  \
        float nv2 = g1 ? b1 : (s); int ni2 = g1 ? i1 : (idx);              \
        float nv1 = g0 ? b0 : (s); int ni1 = g0 ? i0 : (idx);              \
        b3 = g2 ? b2  : (s);  i3 = g2 ? i2  : (idx);                       \
        b2 = g2 ? nv2 : b2;   i2 = g2 ? ni2 : i2;                          \
        b1 = g1 ? nv1 : b1;   i1 = g1 ? ni1 : i1;                          \
        b0 = g0 ? (s) : b0;   i0 = g0 ? (idx) : i0;                        \
    }                                                                      \
} while (0)

// ---------------------------------------------------------------------------
// K1: brute-force scan. Approximate ranking by FMA score
//   s = x*tx + y*ty + z*tz - 0.5*|p|^2   (max s ~ min d2, within ~2e-7)
// Thread = one target; split = half of N staged through smem in 2 chunks.
// Keeps top-4 indices per split; exact reference selection happens in merge.
// ---------------------------------------------------------------------------
__global__ void __launch_bounds__(BLK1) knn_scan(const float* __restrict__ spc,
                                                 const float* __restrict__ tpc) {
    __shared__ float4 tile[CHUNK];

    const int b     = blockIdx.z;
    const int split = blockIdx.y;
    const int m     = blockIdx.x * BLK1 + threadIdx.x;

    const float* tp = tpc + (size_t)(b * MM + m) * 3;
    const float tx = tp[0], ty = tp[1], tz = tp[2];

    float b0 = -CUDART_INF_F, b1 = -CUDART_INF_F, b2 = -CUDART_INF_F, b3 = -CUDART_INF_F;
    int   i0 = 0, i1 = 0, i2 = 0, i3 = 0;

    for (int ph = 0; ph < NPH; ++ph) {            // compile-time 2 phases
        const int nbase = split * LSPLIT + ph * CHUNK;

        __syncthreads();                          // protect tile reuse across phases
        const float* __restrict__ sp = spc + (size_t)(b * NN + nbase) * 3;
        for (int i = threadIdx.x; i < CHUNK; i += BLK1) {
            float x = sp[3 * i + 0], y = sp[3 * i + 1], z = sp[3 * i + 2];
            tile[i] = make_float4(x, y, z, -0.5f * sumsq_ref(x, y, z));
        }
        __syncthreads();

#pragma unroll 4
        for (int i = 0; i < CHUNK; ++i) {
            float4 p = tile[i];   // warp-uniform -> smem broadcast
            float  s = __fmaf_rn(p.x, tx, __fmaf_rn(p.y, ty, __fmaf_rn(p.z, tz, p.w)));
            INS(s, nbase + i);
        }
    }

    g_cand[((size_t)(b * MM + m)) * SPLITS + split] = make_int4(i0, i1, i2, i3);
}

// ---------------------------------------------------------------------------
// K2: merge 2x4 survivors with the EXACT reference key
//   cross = ((x*tx + y*ty) + z*tz) all rn no-fma; d2 = (t2+s2)-(c+c);
//   d = sqrt(max(d2,0)); tie -> lower index (stable top_k).
// Then ref-rounded weights + warp-wide float4 feature blend.
// ---------------------------------------------------------------------------
__device__ __forceinline__ bool key_lt(float dA, int iA, float dB, int iB) {
    return (dA < dB) || (dA == dB && iA < iB);
}

__global__ void __launch_bounds__(256) merge_gather(const float* __restrict__ spc,
                                                    const float* __restrict__ tpc,
                                                    const float* __restrict__ sfeat,
                                                    float* __restrict__ out) {
    const int gwarp = (blockIdx.x * blockDim.x + threadIdx.x) >> 5;
    const int lane  = threadIdx.x & 31;
    const int b     = gwarp / MM;
    const int m     = gwarp % MM;

    const float* tp = tpc + (size_t)(b * MM + m) * 3;
    const float tx = tp[0], ty = tp[1], tz = tp[2];
    const float t2 = sumsq_ref(tx, ty, tz);
    const float* __restrict__ sp = spc + (size_t)b * NN * 3;

    float d0 = CUDART_INF_F, d1 = CUDART_INF_F, d2 = CUDART_INF_F;
    int   i0 = 0x7FFFFFFF,  i1 = 0x7FFFFFFF,  i2 = 0x7FFFFFFF;

#pragma unroll
    for (int sx = 0; sx < SPLITS; ++sx) {
        int4 c4 = g_cand[((size_t)(b * MM + m)) * SPLITS + sx];
#pragma unroll
        for (int j = 0; j < KEEP; ++j) {
            int ix = (j == 0) ? c4.x : (j == 1) ? c4.y : (j == 2) ? c4.z : c4.w;
            float x = sp[3 * ix + 0], y = sp[3 * ix + 1], z = sp[3 * ix + 2];
            // exact reference arithmetic: mul+add cross, rn everywhere
            float c  = __fadd_rn(__fadd_rn(__fmul_rn(x, tx), __fmul_rn(y, ty)),
                                 __fmul_rn(z, tz));
            float dq = __fsub_rn(__fadd_rn(t2, sumsq_ref(x, y, z)), __fadd_rn(c, c));
            float dd = __fsqrt_rn(fmaxf(dq, 0.0f));
            if (key_lt(dd, ix, d2, i2)) {
                if (key_lt(dd, ix, d0, i0))      { d2=d1; i2=i1; d1=d0; i1=i0; d0=dd; i0=ix; }
                else if (key_lt(dd, ix, d1, i1)) { d2=d1; i2=i1; d1=dd; i1=ix; }
                else                             { d2=dd; i2=ix; }
            }
        }
    }

    // w = 1/(d + 1e-6); weight = w / sum(w), ascending-k order, all rn
    float w0 = __fdiv_rn(1.0f, __fadd_rn(d0, 1e-6f));
    float w1 = __fdiv_rn(1.0f, __fadd_rn(d1, 1e-6f));
    float w2 = __fdiv_rn(1.0f, __fadd_rn(d2, 1e-6f));
    float s  = __fadd_rn(__fadd_rn(w0, w1), w2);
    w0 = __fdiv_rn(w0, s);
    w1 = __fdiv_rn(w1, s);
    w2 = __fdiv_rn(w2, s);

    const float4* __restrict__ r0 = (const float4*)(sfeat + (size_t)(b * NN + i0) * FF);
    const float4* __restrict__ r1 = (const float4*)(sfeat + (size_t)(b * NN + i1) * FF);
    const float4* __restrict__ r2 = (const float4*)(sfeat + (size_t)(b * NN + i2) * FF);

    float4 v0 = r0[lane];
    float4 v1 = r1[lane];
    float4 v2 = r2[lane];

    // sum over K ascending, mul then add, all rn (matches jnp.sum)
    float4 o;
    o.x = __fadd_rn(__fadd_rn(__fmul_rn(v0.x, w0), __fmul_rn(v1.x, w1)), __fmul_rn(v2.x, w2));
    o.y = __fadd_rn(__fadd_rn(__fmul_rn(v0.y, w0), __fmul_rn(v1.y, w1)), __fmul_rn(v2.y, w2));
    o.z = __fadd_rn(__fadd_rn(__fmul_rn(v0.z, w0), __fmul_rn(v1.z, w1)), __fmul_rn(v2.z, w2));
    o.w = __fadd_rn(__fadd_rn(__fmul_rn(v0.w, w0), __fmul_rn(v1.w, w1)), __fmul_rn(v2.w, w2));

    float4* op = (float4*)(out + (size_t)(b * MM + m) * FF);
    op[lane] = o;
}

// ---------------------------------------------------------------------------
extern "C" void kernel_launch(void* const* d_in, const int* in_sizes, int n_in,
                              void* d_out, int out_size) {
    const float* source_pc   = (const float*)d_in[0];
    const float* target_pc   = (const float*)d_in[1];
    const float* source_feat = (const float*)d_in[2];
    float*       out         = (float*)d_out;

    dim3 g1(MM / BLK1, SPLITS, BB);   // 128 x 2 x 2 = 512 blocks, 64 thr each
    knn_scan<<<g1, BLK1>>>(source_pc, target_pc);

    const int warps = BB * MM;        // 16384
    merge_gather<<<warps / 8, 256>>>(source_pc, target_pc, source_feat, out);
}

// round 10
// speedup vs baseline: 1.0388x; 1.0368x over previous
#include <cuda_runtime.h>
#include <math_constants.h>

// Problem shape (fixed by setup_inputs)
#define BB 2
#define NN 8192
#define MM 8192
#define FF 128
#define KEEP 4                 // survivors per split (approx-ranking safety)
#define SPLITS 2
#define LSPLIT (NN / SPLITS)   // 4096 candidates per split
#define CHUNK 2048             // smem chunk (32 KB of float4)
#define NPH (LSPLIT / CHUNK)   // 2 phases
#define BLK1 128               // targets per block in scan kernel

// Scratch (no cudaMalloc allowed): survivor indices only
__device__ int4 g_cand[BB * MM * SPLITS];

// Reference-matching sum of squares: ((x*x + y*y) + z*z), all rn, no fma
__device__ __forceinline__ float sumsq_ref(float x, float y, float z) {
    return __fadd_rn(__fadd_rn(__fmul_rn(x, x), __fmul_rn(y, y)), __fmul_rn(z, z));
}

// Branchless sorted insert (descending scores b0>=b1>=b2>=b3). Used ONLY
// inside the warp-voted rare block; per-lane guard may be predicated there.
#define INS(s, idx) do {                                                   \
    if ((s) > b3) {                                                        \
        bool g0 = (s) > b0, g1 = (s) > b1, g2 = (s) > b2;                  \
        float nv2 = g1 ? b1 : (s); int ni2 = g1 ? i1 : (idx);              \
        float nv1 = g0 ? b0 : (s); int ni1 = g0 ? i0 : (idx);              \
        b3 = g2 ? b2  : (s);  i3 = g2 ? i2  : (idx);                       \
        b2 = g2 ? nv2 : b2;   i2 = g2 ? ni2 : i2;                          \
        b1 = g1 ? nv1 : b1;   i1 = g1 ? ni1 : i1;                          \
        b0 = g0 ? (s) : b0;   i0 = g0 ? (idx) : i0;                        \
    }                                                                      \
} while (0)

// ---------------------------------------------------------------------------
// K1: brute-force scan. Approximate ranking by FMA score
//   s = x*tx + y*ty + z*tz - 0.5*|p|^2   (max s ~ min d2, within ~2e-7)
// Warp-aggregated filter: a UNIFORM vote guards the insert block, forcing a
// real uniform branch (no if-conversion of the 25-op SEL chain onto the
// fast path). Top-4 indices per split; exact selection happens in merge.
// ---------------------------------------------------------------------------
__global__ void __launch_bounds__(BLK1) knn_scan(const float* __restrict__ spc,
                                                 const float* __restrict__ tpc) {
    __shared__ float4 tile[CHUNK];

    const int b     = blockIdx.z;
    const int split = blockIdx.y;
    const int m     = blockIdx.x * BLK1 + threadIdx.x;

    const float* tp = tpc + (size_t)(b * MM + m) * 3;
    const float tx = tp[0], ty = tp[1], tz = tp[2];

    float b0 = -CUDART_INF_F, b1 = -CUDART_INF_F, b2 = -CUDART_INF_F, b3 = -CUDART_INF_F;
    int   i0 = 0, i1 = 0, i2 = 0, i3 = 0;

    for (int ph = 0; ph < NPH; ++ph) {            // compile-time 2 phases
        const int nbase = split * LSPLIT + ph * CHUNK;

        __syncthreads();                          // protect tile reuse across phases
        const float* __restrict__ sp = spc + (size_t)(b * NN + nbase) * 3;
        for (int i = threadIdx.x; i < CHUNK; i += BLK1) {
            float x = sp[3 * i + 0], y = sp[3 * i + 1], z = sp[3 * i + 2];
            tile[i] = make_float4(x, y, z, -0.5f * sumsq_ref(x, y, z));
        }
        __syncthreads();

#pragma unroll 4
        for (int i = 0; i < CHUNK; i += 2) {
            float4 pa = tile[i];       // warp-uniform -> smem broadcast
            float4 pb = tile[i + 1];
            float sa = __fmaf_rn(pa.x, tx, __fmaf_rn(pa.y, ty, __fmaf_rn(pa.z, tz, pa.w)));
            float sb = __fmaf_rn(pb.x, tx, __fmaf_rn(pb.y, ty, __fmaf_rn(pb.z, tz, pb.w)));
            // Uniform vote -> real branch; taken ~39% of 2-cand batches
            if (__any_sync(0xffffffffu, fmaxf(sa, sb) > b3)) {
                INS(sa, nbase + i);
                INS(sb, nbase + i + 1);
            }
        }
    }

    g_cand[((size_t)(b * MM + m)) * SPLITS + split] = make_int4(i0, i1, i2, i3);
}

// ---------------------------------------------------------------------------
// K2: merge 2x4 survivors with the EXACT reference key
//   cross = ((x*tx + y*ty) + z*tz) all rn no-fma; d2 = (t2+s2)-(c+c);
//   d = sqrt(max(d2,0)); tie -> lower index (stable top_k).
// Then ref-rounded weights + warp-wide float4 feature blend.
// ---------------------------------------------------------------------------
__device__ __forceinline__ bool key_lt(float dA, int iA, float dB, int iB) {
    return (dA < dB) || (dA == dB && iA < iB);
}

__global__ void __launch_bounds__(256) merge_gather(const float* __restrict__ spc,
                                                    const float* __restrict__ tpc,
                                                    const float* __restrict__ sfeat,
                                                    float* __restrict__ out) {
    const int gwarp = (blockIdx.x * blockDim.x + threadIdx.x) >> 5;
    const int lane  = threadIdx.x & 31;
    const int b     = gwarp / MM;
    const int m     = gwarp % MM;

    const float* tp = tpc + (size_t)(b * MM + m) * 3;
    const float tx = tp[0], ty = tp[1], tz = tp[2];
    const float t2 = sumsq_ref(tx, ty, tz);
    const float* __restrict__ sp = spc + (size_t)b * NN * 3;

    float d0 = CUDART_INF_F, d1 = CUDART_INF_F, d2 = CUDART_INF_F;
    int   i0 = 0x7FFFFFFF,  i1 = 0x7FFFFFFF,  i2 = 0x7FFFFFFF;

#pragma unroll
    for (int sx = 0; sx < SPLITS; ++sx) {
        int4 c4 = g_cand[((size_t)(b * MM + m)) * SPLITS + sx];
#pragma unroll
        for (int j = 0; j < KEEP; ++j) {
            int ix = (j == 0) ? c4.x : (j == 1) ? c4.y : (j == 2) ? c4.z : c4.w;
            float x = sp[3 * ix + 0], y = sp[3 * ix + 1], z = sp[3 * ix + 2];
            // exact reference arithmetic: mul+add cross, rn everywhere
            float c  = __fadd_rn(__fadd_rn(__fmul_rn(x, tx), __fmul_rn(y, ty)),
                                 __fmul_rn(z, tz));
            float dq = __fsub_rn(__fadd_rn(t2, sumsq_ref(x, y, z)), __fadd_rn(c, c));
            float dd = __fsqrt_rn(fmaxf(dq, 0.0f));
            if (key_lt(dd, ix, d2, i2)) {
                if (key_lt(dd, ix, d0, i0))      { d2=d1; i2=i1; d1=d0; i1=i0; d0=dd; i0=ix; }
                else if (key_lt(dd, ix, d1, i1)) { d2=d1; i2=i1; d1=dd; i1=ix; }
                else                             { d2=dd; i2=ix; }
            }
        }
    }

    // w = 1/(d + 1e-6); weight = w / sum(w), ascending-k order, all rn
    float w0 = __fdiv_rn(1.0f, __fadd_rn(d0, 1e-6f));
    float w1 = __fdiv_rn(1.0f, __fadd_rn(d1, 1e-6f));
    float w2 = __fdiv_rn(1.0f, __fadd_rn(d2, 1e-6f));
    float s  = __fadd_rn(__fadd_rn(w0, w1), w2);
    w0 = __fdiv_rn(w0, s);
    w1 = __fdiv_rn(w1, s);
    w2 = __fdiv_rn(w2, s);

    const float4* __restrict__ r0 = (const float4*)(sfeat + (size_t)(b * NN + i0) * FF);
    const float4* __restrict__ r1 = (const float4*)(sfeat + (size_t)(b * NN + i1) * FF);
    const float4* __restrict__ r2 = (const float4*)(sfeat + (size_t)(b * NN + i2) * FF);

    float4 v0 = r0[lane];
    float4 v1 = r1[lane];
    float4 v2 = r2[lane];

    // sum over K ascending, mul then add, all rn (matches jnp.sum)
    float4 o;
    o.x = __fadd_rn(__fadd_rn(__fmul_rn(v0.x, w0), __fmul_rn(v1.x, w1)), __fmul_rn(v2.x, w2));
    o.y = __fadd_rn(__fadd_rn(__fmul_rn(v0.y, w0), __fmul_rn(v1.y, w1)), __fmul_rn(v2.y, w2));
    o.z = __fadd_rn(__fadd_rn(__fmul_rn(v0.z, w0), __fmul_rn(v1.z, w1)), __fmul_rn(v2.z, w2));
    o.w = __fadd_rn(__fadd_rn(__fmul_rn(v0.w, w0), __fmul_rn(v1.w, w1)), __fmul_rn(v2.w, w2));

    float4* op = (float4*)(out + (size_t)(b * MM + m) * FF);
    op[lane] = o;
}

// ---------------------------------------------------------------------------
extern "C" void kernel_launch(void* const* d_in, const int* in_sizes, int n_in,
                              void* d_out, int out_size) {
    const float* source_pc   = (const float*)d_in[0];
    const float* target_pc   = (const float*)d_in[1];
    const float* source_feat = (const float*)d_in[2];
    float*       out         = (float*)d_out;

    dim3 g1(MM / BLK1, SPLITS, BB);   // 64 x 2 x 2 = 256 blocks, 128 thr each
    knn_scan<<<g1, BLK1>>>(source_pc, target_pc);

    const int warps = BB * MM;        // 16384
    merge_gather<<<warps / 8, 256>>>(source_pc, target_pc, source_feat, out);
}